// round 15
// baseline (speedup 1.0000x reference)
#include <cuda_runtime.h>
#include <cuda_fp16.h>
#include <cstdint>

typedef uint32_t u32;

#define HN 50
#define TN 512
#define NCTA 128
#define NTHR 640          // 13 MMA warps (tid<416) + 7 act warps

#define BROW 272
#define BT   (8*BROW)     // 2176 bytes, one group tile (8 elems x 136 cols fp16)
// tile cols: 0-7 = x, 8-57 = h0, 58 = const 1 (bias), 59-108 = h1, 109-135 pad
#define GST  10           // gates row stride (f32 words)
#define GSEC (208*GST)    // words per (group,layer) gate section

#define SM_B    0                       // 2 tiles = 4352
#define SM_G    4352                    // 4 * GSEC * 4 = 33280
#define SM_WL   (SM_G + 4*GSEC*4)       // 37632
#define SM_HEAD (SM_WL + 256)           // 37888 : [50][16] f32
#define SMEM_BYTES (SM_HEAD + 3200)     // 41088

__device__ __forceinline__ u32 smem_u32(const void* p){
    u32 a; asm("{ .reg .u64 t; cvta.to.shared.u64 t, %1; cvt.u32.u64 %0, t; }" : "=r"(a) : "l"(p));
    return a;
}
__device__ __forceinline__ u32 pk2h(__half a, __half b){
    return (u32)__half_as_ushort(a) | ((u32)__half_as_ushort(b) << 16);
}
__device__ __forceinline__ void mma_f16(float* c, const u32* a, u32 b0, u32 b1){
    asm volatile("mma.sync.aligned.m16n8k16.row.col.f32.f16.f16.f32 "
                 "{%0,%1,%2,%3}, {%4,%5,%6,%7}, {%8,%9}, {%0,%1,%2,%3};"
                 : "+f"(c[0]), "+f"(c[1]), "+f"(c[2]), "+f"(c[3])
                 : "r"(a[0]), "r"(a[1]), "r"(a[2]), "r"(a[3]), "r"(b0), "r"(b1));
}
__device__ __forceinline__ void ldsm4(u32* r, u32 addr){
    asm volatile("ldmatrix.sync.aligned.m8n8.x4.shared.b16 {%0,%1,%2,%3}, [%4];"
                 : "=r"(r[0]), "=r"(r[1]), "=r"(r[2]), "=r"(r[3]) : "r"(addr));
}
__device__ __forceinline__ float tanha(float v){
    float r; asm("tanh.approx.f32 %0, %1;" : "=f"(r) : "f"(v)); return r;
}
__device__ __forceinline__ float siga(float v){
    return fmaf(0.5f, tanha(0.5f * v), 0.5f);
}
__device__ __forceinline__ void bar_sync(int id){
    asm volatile("bar.sync %0, %1;" :: "r"(id), "n"(NTHR) : "memory");
}
__device__ __forceinline__ void bar_arrive(int id){
    asm volatile("bar.arrive %0, %1;" :: "r"(id), "n"(NTHR) : "memory");
}
// barrier ids: GB_g = 1+g (gates ready), HB_g = 3+g (h/x ready)

// A-row mapping (M16/warp, unit-interleaved): warp w, local row r:
// unit u = 4w + (r>>2), gate t = r&3; bias folded at k=58
__device__ __forceinline__ float a0elem(int w, int r, int k,
                                        const float* Whh0, const float* Wih0,
                                        const float* bih0, const float* bhh0){
    const int u = 4*w + (r >> 2), t = r & 3;
    if (u >= HN) return 0.f;
    const int g = t * 50 + u;
    if (k < 8)   return Wih0[g * 8 + k];
    if (k < 58)  return Whh0[g * 50 + (k - 8)];
    if (k == 58) return bih0[g] + bhh0[g];
    return 0.f;
}
__device__ __forceinline__ float a1elem(int w, int r, int k,
                                        const float* Wih1, const float* Whh1,
                                        const float* bih1, const float* bhh1){
    const int u = 4*w + (r >> 2), t = r & 3;
    if (u >= HN) return 0.f;
    const int g = t * 50 + u;
    if (k >= 8 && k < 58)   return Wih1[g * 50 + (k - 8)];
    if (k == 58)            return bih1[g] + bhh1[g];
    if (k >= 59 && k < 109) return Whh1[g * 50 + (k - 59)];
    return 0.f;
}

__global__ void __launch_bounds__(NTHR, 1)
lstm_ws_kernel(const float* __restrict__ x,
               const float* __restrict__ Wih0, const float* __restrict__ Whh0,
               const float* __restrict__ bih0, const float* __restrict__ bhh0,
               const float* __restrict__ Wih1, const float* __restrict__ Whh1,
               const float* __restrict__ bih1, const float* __restrict__ bhh1,
               const float* __restrict__ Wlin, const float* __restrict__ blin,
               float* __restrict__ out)
{
    extern __shared__ char sm[];
    const u32 smb = smem_u32(sm);
    const int tid  = threadIdx.x;
    const int cta  = blockIdx.x;
    const int lane = tid & 31;
    const int wrp  = tid >> 5;
    const bool isMMA = (tid < 416);

    float* wl = (float*)(sm + SM_WL);
    float* G  = (float*)(sm + SM_G);

    // ---- prologue: zero tiles ----
    for (int i = tid; i < 2 * BT / 4; i += NTHR)
        ((u32*)(sm + SM_B))[i] = 0;
    if (tid < HN) wl[tid] = Wlin[tid];
    if (tid == HN) wl[HN] = blin[0];
    __syncthreads();

    // bias col 58 = 1.0 in both tiles (written once, never overwritten)
    if (tid < 16)
        *(__half*)(sm + SM_B + (tid >> 3) * BT + (tid & 7) * BROW + 58 * 2) = __float2half_rn(1.f);

    // ---- MMA-warp setup ----
    const int gid = lane >> 2;
    const int c0  = (lane & 3) * 2;
    u32 A0[4][4], A1[7][4];
    const int ln8 = lane & 7, grp = lane >> 3;
    const u32 bOffLane = (u32)(ln8 * BROW + (grp & 1) * 16 + (grp >> 1) * 32);
    if (isMMA){
#pragma unroll
        for (int kt = 0; kt < 7; ++kt)
#pragma unroll
            for (int q = 0; q < 4; ++q){
                const int r = gid + ((q & 1) ? 8 : 0);
                const int k = kt * 16 + c0 + ((q & 2) ? 8 : 0);
                A1[kt][q] = pk2h(__float2half_rn(a1elem(wrp, r, k,     Wih1, Whh1, bih1, bhh1)),
                                 __float2half_rn(a1elem(wrp, r, k + 1, Wih1, Whh1, bih1, bhh1)));
                if (kt < 4)
                    A0[kt][q] = pk2h(__float2half_rn(a0elem(wrp, r, k,     Whh0, Wih0, bih0, bhh0)),
                                     __float2half_rn(a0elem(wrp, r, k + 1, Whh0, Wih0, bih0, bhh0)));
            }
    }

    // ---- act-warp setup ----
    const int a  = tid - 416;              // 0..223 for act warps
    const int au = (a >= 0) ? (a % 50) : 0;     // unit
    const int aj = (a >= 0) ? (a / 50) : 0;     // elem-pair 0..3
    const int e2 = 2 * aj;
    const int rowu = 16 * (au >> 2) + 4 * (au & 3);
    const bool doAct = (!isMMA) && (a < 200);
    float cc[8] = {0,0,0,0,0,0,0,0};       // [g*4 + lay*2 + m]

    // x stagers: act threads a<64: e = a>>3, d = a&7, both groups
    const int xe = (a >= 0) ? (a >> 3) : 0;
    const int xd = (a >= 0) ? (a & 7) : 0;
    const bool doX = (!isMMA) && (a < 64);
    const float* xgp[2];
    xgp[0] = x + ((size_t)(cta * 16 + xe) * TN) * 8 + xd;
    xgp[1] = x + ((size_t)(cta * 16 + 8 + xe) * TN) * 8 + xd;
    float xv[2] = {0.f, 0.f};
    if (doX){
        // stage x_A(0), x_B(0); prefetch x(1)
        *(__half*)(sm + SM_B + 0 * BT + xe * BROW + xd * 2) = __float2half_rn(xgp[0][0]);
        *(__half*)(sm + SM_B + 1 * BT + xe * BROW + xd * 2) = __float2half_rn(xgp[1][0]);
        xv[0] = xgp[0][8];
        xv[1] = xgp[1][8];
    }

    __syncthreads();   // all staging + tiles visible to everyone

    if (isMMA){
        // =========== producer loop: slot s -> group g = s&1, step p = s>>1 ===========
        for (int s = 0; s < 2 * TN + 2; ++s){
            const int g = s & 1;
            bar_sync(3 + g);               // h/x of group g ready

            float a0a[4] = {0,0,0,0}, a0b[4] = {0,0,0,0};
            float a1a[4] = {0,0,0,0}, a1b[4] = {0,0,0,0};
            const u32 bhA = smb + SM_B + (u32)(g * BT) + bOffLane;
#pragma unroll
            for (int i = 0; i < 4; ++i){   // kt pair {2i, 2i+1}
                u32 bh[4];
                ldsm4(bh, bhA + i * 64);
                const int k0 = 2 * i, k1 = 2 * i + 1;
                float* q1 = (i & 1) ? a1b : a1a;
                mma_f16(q1, A1[k0], bh[0], bh[1]);
                if (k1 < 7) mma_f16(q1, A1[k1], bh[2], bh[3]);
                if (k0 < 4){
                    float* q0 = (i & 1) ? a0b : a0a;
                    mma_f16(q0, A0[k0], bh[0], bh[1]);
                    mma_f16(q0, A0[k1], bh[2], bh[3]);
                }
            }
            // STS gates: storage row = 16*wrp + r  (r = warp-tile row)
            {
                float* G0 = G + (g * 2 + 0) * GSEC;
                float* G1 = G + (g * 2 + 1) * GSEC;
                const int rw = 16 * wrp;
                *(float2*)(G0 + (rw + gid)     * GST + c0) = make_float2(a0a[0] + a0b[0], a0a[1] + a0b[1]);
                *(float2*)(G0 + (rw + gid + 8) * GST + c0) = make_float2(a0a[2] + a0b[2], a0a[3] + a0b[3]);
                *(float2*)(G1 + (rw + gid)     * GST + c0) = make_float2(a1a[0] + a1b[0], a1a[1] + a1b[1]);
                *(float2*)(G1 + (rw + gid + 8) * GST + c0) = make_float2(a1a[2] + a1b[2], a1a[3] + a1b[3]);
            }
            bar_arrive(1 + g);             // gates of group g ready
        }
    } else {
        // =========== consumer loop ===========
        bar_arrive(3);                     // prime HB_A
        bar_arrive(4);                     // prime HB_B
        for (int s = 0; s < 2 * TN + 2; ++s){
            const int g = s & 1;
            const int p = s >> 1;
            bar_sync(1 + g);               // gates(g, p) ready

            char* tb = sm + SM_B + g * BT;
            if (doAct){
#pragma unroll
                for (int lay = 0; lay < 2; ++lay){
                    if (lay == 0 ? (p >= TN) : (p < 1)) continue;
                    const float* Gs = G + (g * 2 + lay) * GSEC;
                    const float2 gi = *(const float2*)(Gs + (rowu + 0) * GST + e2);
                    const float2 gf = *(const float2*)(Gs + (rowu + 1) * GST + e2);
                    const float2 gg = *(const float2*)(Gs + (rowu + 2) * GST + e2);
                    const float2 go = *(const float2*)(Gs + (rowu + 3) * GST + e2);
                    float& c0r = cc[g * 4 + lay * 2 + 0];
                    float& c1r = cc[g * 4 + lay * 2 + 1];
                    const float i0 = siga(gi.x), f0 = siga(gf.x);
                    const float q0 = tanha(gg.x), o0 = siga(go.x);
                    c0r = fmaf(f0, c0r, i0 * q0);
                    const float v0 = o0 * tanha(c0r);
                    const float i1 = siga(gi.y), f1 = siga(gf.y);
                    const float q1 = tanha(gg.y), o1 = siga(go.y);
                    c1r = fmaf(f1, c1r, i1 * q1);
                    const float v1 = o1 * tanha(c1r);
                    if (lay == 1 && p == TN){
                        float* hd = (float*)(sm + SM_HEAD);
                        hd[au * 16 + g * 8 + e2]     = v0;
                        hd[au * 16 + g * 8 + e2 + 1] = v1;
                    } else {
                        const int col = lay ? (59 + au) : (8 + au);
                        *(__half*)(tb + (e2)     * BROW + col * 2) = __float2half_rn(v0);
                        *(__half*)(tb + (e2 + 1) * BROW + col * 2) = __float2half_rn(v1);
                    }
                }
            }
            // stage x_g(p+1), prefetch x_g(p+2)
            if (doX && (p + 1) < TN){
                *(__half*)(tb + xe * BROW + xd * 2) = __float2half_rn(xv[g]);
                int tn = p + 2; if (tn > TN - 1) tn = TN - 1;
                xv[g] = xgp[g][(size_t)tn * 8];
            }
            if (s < 2 * TN)                // balance arrival counts (last 2 slots unused)
                bar_arrive(3 + g);
        }
    }

    __syncthreads();

    // ---- linear head on stashed final h1 ----
    if (tid < 16){
        const float* hd = (const float*)(sm + SM_HEAD);
        float acc = wl[HN];
#pragma unroll 10
        for (int j = 0; j < HN; ++j)
            acc = fmaf(hd[j * 16 + tid], wl[j], acc);
        out[cta * 16 + tid] = acc;
    }
}

extern "C" void kernel_launch(void* const* d_in, const int* in_sizes, int n_in,
                              void* d_out, int out_size)
{
    const float* x    = (const float*)d_in[0];
    const float* Wih0 = (const float*)d_in[1];
    const float* Whh0 = (const float*)d_in[2];
    const float* bih0 = (const float*)d_in[3];
    const float* bhh0 = (const float*)d_in[4];
    const float* Wih1 = (const float*)d_in[5];
    const float* Whh1 = (const float*)d_in[6];
    const float* bih1 = (const float*)d_in[7];
    const float* bhh1 = (const float*)d_in[8];
    const float* Wlin = (const float*)d_in[9];
    const float* blin = (const float*)d_in[10];
    float* out = (float*)d_out;

    cudaFuncSetAttribute(lstm_ws_kernel,
                         cudaFuncAttributeMaxDynamicSharedMemorySize, SMEM_BYTES);
    lstm_ws_kernel<<<NCTA, NTHR, SMEM_BYTES>>>(
        x, Wih0, Whh0, bih0, bhh0, Wih1, Whh1, bih1, bhh1, Wlin, blin, out);
}

// round 16
// speedup vs baseline: 2.0873x; 2.0873x over previous
#include <cuda_runtime.h>
#include <cuda_fp16.h>
#include <cstdint>

typedef uint32_t u32;

#define HN 50
#define TN 512
#define NCTA 296          // 24 CTAs x 6 elems + 272 x 7 = 2048
#define NTHR 416          // 13 warps, M16 per warp

#define BROW 272
#define BT   (8*BROW)     // 2176B, 8-row fp16 tile
// tile cols: 0-7 = x, 8-57 = h0, 58 = const 1 (bias), 59-108 = h1, 109-135 pad
#define SM_B    0                 // 2 tiles = 4352
#define SM_G    4352              // 13 warps * 160 u32 (half2 gates) = 8320
#define SM_WL   12672             // 51 f32 -> 256
#define SM_HEAD 12928             // [50][8] f32 = 1600
#define SMEM_BYTES 14528

__device__ __forceinline__ u32 smem_u32(const void* p){
    u32 a; asm("{ .reg .u64 t; cvta.to.shared.u64 t, %1; cvt.u32.u64 %0, t; }" : "=r"(a) : "l"(p));
    return a;
}
__device__ __forceinline__ u32 pk2h(__half a, __half b){
    return (u32)__half_as_ushort(a) | ((u32)__half_as_ushort(b) << 16);
}
__device__ __forceinline__ void mma_f16(float* c, const u32* a, u32 b0, u32 b1){
    asm volatile("mma.sync.aligned.m16n8k16.row.col.f32.f16.f16.f32 "
                 "{%0,%1,%2,%3}, {%4,%5,%6,%7}, {%8,%9}, {%0,%1,%2,%3};"
                 : "+f"(c[0]), "+f"(c[1]), "+f"(c[2]), "+f"(c[3])
                 : "r"(a[0]), "r"(a[1]), "r"(a[2]), "r"(a[3]), "r"(b0), "r"(b1));
}
__device__ __forceinline__ void ldsm4(u32* r, u32 addr){
    asm volatile("ldmatrix.sync.aligned.m8n8.x4.shared.b16 {%0,%1,%2,%3}, [%4];"
                 : "=r"(r[0]), "=r"(r[1]), "=r"(r[2]), "=r"(r[3]) : "r"(addr));
}
__device__ __forceinline__ float tanha(float v){
    float r; asm("tanh.approx.f32 %0, %1;" : "=f"(r) : "f"(v)); return r;
}
__device__ __forceinline__ float siga(float v){
    return fmaf(0.5f, tanha(0.5f * v), 0.5f);
}

// A-row mapping (M16/warp, unit-interleaved): warp w, local row r:
// unit u = 4w + (r>>2), gate t = r&3; bias folded at k=58
__device__ __forceinline__ float a0elem(int u, int t, int k,
                                        const float* Whh0, const float* Wih0,
                                        const float* bih0, const float* bhh0){
    if (u >= HN) return 0.f;
    const int g = t * 50 + u;
    if (k < 8)   return Wih0[g * 8 + k];
    if (k < 58)  return Whh0[g * 50 + (k - 8)];
    if (k == 58) return bih0[g] + bhh0[g];
    return 0.f;
}
__device__ __forceinline__ float a1elem(int u, int t, int k,
                                        const float* Wih1, const float* Whh1,
                                        const float* bih1, const float* bhh1){
    if (u >= HN) return 0.f;
    const int g = t * 50 + u;
    if (k >= 8 && k < 58)   return Wih1[g * 50 + (k - 8)];
    if (k == 58)            return bih1[g] + bhh1[g];
    if (k >= 59 && k < 109) return Whh1[g * 50 + (k - 59)];
    return 0.f;
}

__global__ void __launch_bounds__(NTHR, 2)
lstm_mma9_kernel(const float* __restrict__ x,
                 const float* __restrict__ Wih0, const float* __restrict__ Whh0,
                 const float* __restrict__ bih0, const float* __restrict__ bhh0,
                 const float* __restrict__ Wih1, const float* __restrict__ Whh1,
                 const float* __restrict__ bih1, const float* __restrict__ bhh1,
                 const float* __restrict__ Wlin, const float* __restrict__ blin,
                 float* __restrict__ out)
{
    extern __shared__ char sm[];
    const u32 smb = smem_u32(sm);
    const int tid  = threadIdx.x;
    const int cta  = blockIdx.x;
    const int lane = tid & 31;
    const int wrp  = tid >> 5;

    // balanced batch mapping: first 24 CTAs take 6 elems, rest take 7
    const int cnt   = (cta < 24) ? 6 : 7;
    const int start = (cta < 24) ? (cta * 6) : (144 + (cta - 24) * 7);

    float* wl = (float*)(sm + SM_WL);

    // ---- init: zero tiles, head weights ----
    for (int i = tid; i < 2 * BT / 4; i += NTHR)
        ((u32*)(sm + SM_B))[i] = 0;
    if (tid < HN) wl[tid] = Wlin[tid];
    if (tid == HN) wl[HN] = blin[0];

    // ---- register A fragments (fp16; unit-interleaved rows; bias col) ----
    const int gid = lane >> 2;
    const int c0  = (lane & 3) * 2;
    u32 A0[4][4], A1[7][4];
#pragma unroll
    for (int kt = 0; kt < 7; ++kt)
#pragma unroll
        for (int q = 0; q < 4; ++q){
            const int r = gid + ((q & 1) ? 8 : 0);
            const int k = kt * 16 + c0 + ((q & 2) ? 8 : 0);
            const int u = 4 * wrp + (r >> 2), t = r & 3;
            A1[kt][q] = pk2h(__float2half_rn(a1elem(u, t, k,     Wih1, Whh1, bih1, bhh1)),
                             __float2half_rn(a1elem(u, t, k + 1, Wih1, Whh1, bih1, bhh1)));
            if (kt < 4)
                A0[kt][q] = pk2h(__float2half_rn(a0elem(u, t, k,     Whh0, Wih0, bih0, bhh0)),
                                 __float2half_rn(a0elem(u, t, k + 1, Whh0, Wih0, bih0, bhh0)));
        }

    // ---- ldsm lane offsets: x4 covers kt pair {2i, 2i+1} ----
    const int ln8 = lane & 7, grp = lane >> 3;
    const u32 bOffLane = (u32)(ln8 * BROW + (grp & 1) * 16 + (grp >> 1) * 32);

    // ---- act roles: lane = up*8 + e ----
    const int e  = lane & 7;
    const int up = lane >> 3;              // 0..3
    const int au = 4 * wrp + up;           // unit (valid if < 50)
    u32* gw32 = (u32*)(sm + SM_G) + wrp * 160;   // [2 lay][16 rows][5 half2-words]

    // ---- x staging roles: tid<64 -> (xe, xd); active only for xe<cnt ----
    const int xd = tid & 7, xe = tid >> 3;
    const bool doX = (tid < 64) && (xe < cnt);
    const float* xgp = doX ? (x + ((size_t)(start + xe) * TN) * 8 + xd) : x;

    __syncthreads();   // zeroing done

    // bias col 58 = 1.0 in both tiles (written once); x(0) into buf0; prefetch x(1)
    if (tid < 16)
        *(__half*)(sm + SM_B + (tid >> 3) * BT + (tid & 7) * BROW + 58 * 2) = __float2half_rn(1.f);
    float xv = 0.f;
    if (doX){
        *(__half*)(sm + SM_B + xe * BROW + xd * 2) = __float2half_rn(xgp[0]);
        xv = xgp[8];
    }

    float cc0 = 0.f, cc1 = 0.f;

    // ================= phase loop (one barrier per phase) =================
    for (int p = 0; p <= TN; ++p){
        const int b = p & 1, nb = b ^ 1;

        __syncthreads();   // B[b] ready (incl. bias col / x0 on first pass); B[nb] free

        // ---------------- MMA: single pass fp16, N=8 ----------------
        float acc0[4] = {0,0,0,0};
        float acc1[4] = {0,0,0,0};
        {
            const u32 bhA = smb + SM_B + (u32)(b * BT) + bOffLane;
#pragma unroll
            for (int i = 0; i < 4; ++i){   // kt pair {2i, 2i+1}
                u32 bh[4];
                ldsm4(bh, bhA + i * 64);
                const int k0 = 2 * i, k1 = 2 * i + 1;
                mma_f16(acc1, A1[k0], bh[0], bh[1]);
                if (k1 < 7) mma_f16(acc1, A1[k1], bh[2], bh[3]);
                if (k0 < 4) mma_f16(acc0, A0[k0], bh[0], bh[1]);
                if (k1 < 4) mma_f16(acc0, A0[k1], bh[2], bh[3]);
            }
        }

        // ---------------- gates -> warp-private scratch (half2) ----------------
        {
            const int j4 = lane & 3;
            const __half2 h00 = __floats2half2_rn(acc0[0], acc0[1]);
            const __half2 h01 = __floats2half2_rn(acc0[2], acc0[3]);
            const __half2 h10 = __floats2half2_rn(acc1[0], acc1[1]);
            const __half2 h11 = __floats2half2_rn(acc1[2], acc1[3]);
            gw32[gid * 5 + j4]            = *(const u32*)&h00;
            gw32[(gid + 8) * 5 + j4]      = *(const u32*)&h01;
            gw32[80 + gid * 5 + j4]       = *(const u32*)&h10;
            gw32[80 + (gid + 8) * 5 + j4] = *(const u32*)&h11;
        }
        __syncwarp(0xffffffffu);

        // ---------------- activations (warp-local, MUFU.TANH) ----------------
        char* bwh = sm + SM_B + nb * BT;
        if (au < HN){
            const int ws = e >> 1, odd = e & 1;
#pragma unroll
            for (int lay = 0; lay < 2; ++lay){
                if (lay == 0 ? (p >= TN) : (p < 1)) continue;
                const u32* gr = gw32 + lay * 80;
                const u32 wi = gr[(4 * up + 0) * 5 + ws];
                const u32 wf = gr[(4 * up + 1) * 5 + ws];
                const u32 wg = gr[(4 * up + 2) * 5 + ws];
                const u32 wo = gr[(4 * up + 3) * 5 + ws];
                const float2 fi = __half22float2(*(const __half2*)&wi);
                const float2 ff = __half22float2(*(const __half2*)&wf);
                const float2 fg = __half22float2(*(const __half2*)&wg);
                const float2 fo = __half22float2(*(const __half2*)&wo);
                const float gi = odd ? fi.y : fi.x;
                const float gf = odd ? ff.y : ff.x;
                const float gg = odd ? fg.y : fg.x;
                const float go = odd ? fo.y : fo.x;
                const float i_ = siga(gi), f_ = siga(gf);
                const float q_ = tanha(gg), o_ = siga(go);
                float& c = lay ? cc1 : cc0;
                c = fmaf(f_, c, i_ * q_);
                const float v = o_ * tanha(c);
                if (lay == 1 && p == TN){
                    ((float*)(sm + SM_HEAD))[au * 8 + e] = v;   // final h1 stash
                } else {
                    const int col = lay ? (59 + au) : (8 + au);
                    *(__half*)(bwh + e * BROW + col * 2) = __float2half_rn(v);
                }
            }
        }

        // ---------------- x staging: x(p+1) -> buf nb ----------------
        if (doX && (p + 1) < TN){
            *(__half*)(bwh + xe * BROW + xd * 2) = __float2half_rn(xv);
            int tn = p + 2; if (tn > TN - 1) tn = TN - 1;
            xv = xgp[(size_t)tn * 8];
        }
    }

    __syncthreads();

    // ---- linear head on stashed final h1 ----
    if (tid < cnt){
        const float* hd = (const float*)(sm + SM_HEAD);
        float acc = wl[HN];
#pragma unroll 10
        for (int j = 0; j < HN; ++j)
            acc = fmaf(hd[j * 8 + tid], wl[j], acc);
        out[start + tid] = acc;
    }
}

extern "C" void kernel_launch(void* const* d_in, const int* in_sizes, int n_in,
                              void* d_out, int out_size)
{
    const float* x    = (const float*)d_in[0];
    const float* Wih0 = (const float*)d_in[1];
    const float* Whh0 = (const float*)d_in[2];
    const float* bih0 = (const float*)d_in[3];
    const float* bhh0 = (const float*)d_in[4];
    const float* Wih1 = (const float*)d_in[5];
    const float* Whh1 = (const float*)d_in[6];
    const float* bih1 = (const float*)d_in[7];
    const float* bhh1 = (const float*)d_in[8];
    const float* Wlin = (const float*)d_in[9];
    const float* blin = (const float*)d_in[10];
    float* out = (float*)d_out;

    cudaFuncSetAttribute(lstm_mma9_kernel,
                         cudaFuncAttributeMaxDynamicSharedMemorySize, SMEM_BYTES);
    lstm_mma9_kernel<<<NCTA, NTHR, SMEM_BYTES>>>(
        x, Wih0, Whh0, bih0, bhh0, Wih1, Whh1, bih1, bhh1, Wlin, blin, out);
}

// round 17
// speedup vs baseline: 2.1316x; 1.0213x over previous
#include <cuda_runtime.h>
#include <cuda_fp16.h>
#include <cstdint>

typedef uint32_t u32;

#define HN 50
#define TN 512
#define NCTA 296          // 24 CTAs x 6 elems + 272 x 7 = 2048
#define NTHR 416          // 13 warps, M16 per warp

#define BROW 272
#define BT   (8*BROW)     // 2176B, 8-row fp16 tile
// tile cols: 0-7 = x, 8-57 = h0, 58 = const 1 (bias), 59-108 = h1, 109-135 pad
#define SM_B    0                 // 2 tiles = 4352
#define SM_G    4352              // 13 warps * 160 u32 (half2 gates) = 8320
#define SM_WL   12672             // 51 f32 -> 256
#define SM_HEAD 12928             // [50][8] f32 = 1600
#define SMEM_BYTES 14528

__device__ __forceinline__ u32 smem_u32(const void* p){
    u32 a; asm("{ .reg .u64 t; cvta.to.shared.u64 t, %1; cvt.u32.u64 %0, t; }" : "=r"(a) : "l"(p));
    return a;
}
__device__ __forceinline__ u32 pk2h(__half a, __half b){
    return (u32)__half_as_ushort(a) | ((u32)__half_as_ushort(b) << 16);
}
__device__ __forceinline__ void mma_f16(float* c, const u32* a, u32 b0, u32 b1){
    asm volatile("mma.sync.aligned.m16n8k16.row.col.f32.f16.f16.f32 "
                 "{%0,%1,%2,%3}, {%4,%5,%6,%7}, {%8,%9}, {%0,%1,%2,%3};"
                 : "+f"(c[0]), "+f"(c[1]), "+f"(c[2]), "+f"(c[3])
                 : "r"(a[0]), "r"(a[1]), "r"(a[2]), "r"(a[3]), "r"(b0), "r"(b1));
}
__device__ __forceinline__ void ldsm4(u32* r, u32 addr){
    asm volatile("ldmatrix.sync.aligned.m8n8.x4.shared.b16 {%0,%1,%2,%3}, [%4];"
                 : "=r"(r[0]), "=r"(r[1]), "=r"(r[2]), "=r"(r[3]) : "r"(addr));
}
__device__ __forceinline__ void ldsm2(u32* r, u32 addr){
    asm volatile("ldmatrix.sync.aligned.m8n8.x2.shared.b16 {%0,%1}, [%2];"
                 : "=r"(r[0]), "=r"(r[1]) : "r"(addr));
}
__device__ __forceinline__ float tanha(float v){
    float r; asm("tanh.approx.f32 %0, %1;" : "=f"(r) : "f"(v)); return r;
}

// A-row mapping (M16/warp, unit-interleaved): warp w, local row r:
// unit u = 4w + (r>>2), gate t = r&3; bias folded at k=58.
// Scale 0.5 folded into i/f/o rows (t != 2) so sigmoid = 0.5*tanh(g)+0.5.
__device__ __forceinline__ float a0elem(int u, int t, int k,
                                        const float* Whh0, const float* Wih0,
                                        const float* bih0, const float* bhh0){
    if (u >= HN) return 0.f;
    const int g = t * 50 + u;
    const float s = (t == 2) ? 1.f : 0.5f;
    if (k < 8)   return s * Wih0[g * 8 + k];
    if (k < 58)  return s * Whh0[g * 50 + (k - 8)];
    if (k == 58) return s * (bih0[g] + bhh0[g]);
    return 0.f;
}
__device__ __forceinline__ float a1elem(int u, int t, int k,
                                        const float* Wih1, const float* Whh1,
                                        const float* bih1, const float* bhh1){
    if (u >= HN) return 0.f;
    const int g = t * 50 + u;
    const float s = (t == 2) ? 1.f : 0.5f;
    if (k >= 8 && k < 58)   return s * Wih1[g * 50 + (k - 8)];
    if (k == 58)            return s * (bih1[g] + bhh1[g]);
    if (k >= 59 && k < 109) return s * Whh1[g * 50 + (k - 59)];
    return 0.f;
}

__global__ void __launch_bounds__(NTHR, 2)
lstm_mma10_kernel(const float* __restrict__ x,
                  const float* __restrict__ Wih0, const float* __restrict__ Whh0,
                  const float* __restrict__ bih0, const float* __restrict__ bhh0,
                  const float* __restrict__ Wih1, const float* __restrict__ Whh1,
                  const float* __restrict__ bih1, const float* __restrict__ bhh1,
                  const float* __restrict__ Wlin, const float* __restrict__ blin,
                  float* __restrict__ out)
{
    extern __shared__ char sm[];
    const u32 smb = smem_u32(sm);
    const int tid  = threadIdx.x;
    const int cta  = blockIdx.x;
    const int lane = tid & 31;
    const int wrp  = tid >> 5;

    // balanced batch mapping: first 24 CTAs take 6 elems, rest take 7
    const int cnt   = (cta < 24) ? 6 : 7;
    const int start = (cta < 24) ? (cta * 6) : (144 + (cta - 24) * 7);

    float* wl = (float*)(sm + SM_WL);

    // ---- init: zero tiles, head weights ----
    for (int i = tid; i < 2 * BT / 4; i += NTHR)
        ((u32*)(sm + SM_B))[i] = 0;
    if (tid < HN) wl[tid] = Wlin[tid];
    if (tid == HN) wl[HN] = blin[0];

    // ---- register A fragments (fp16; unit-interleaved; bias col; 0.5 folded) ----
    const int gid = lane >> 2;
    const int c0  = (lane & 3) * 2;
    u32 A0[4][4], A1[7][4];
#pragma unroll
    for (int kt = 0; kt < 7; ++kt)
#pragma unroll
        for (int q = 0; q < 4; ++q){
            const int r = gid + ((q & 1) ? 8 : 0);
            const int k = kt * 16 + c0 + ((q & 2) ? 8 : 0);
            const int u = 4 * wrp + (r >> 2), t = r & 3;
            A1[kt][q] = pk2h(__float2half_rn(a1elem(u, t, k,     Wih1, Whh1, bih1, bhh1)),
                             __float2half_rn(a1elem(u, t, k + 1, Wih1, Whh1, bih1, bhh1)));
            if (kt < 4)
                A0[kt][q] = pk2h(__float2half_rn(a0elem(u, t, k,     Whh0, Wih0, bih0, bhh0)),
                                 __float2half_rn(a0elem(u, t, k + 1, Whh0, Wih0, bih0, bhh0)));
        }

    // ---- ldsm lane offsets: x4 covers kt pair {2i, 2i+1} ----
    const int ln8 = lane & 7, grp = lane >> 3;
    const u32 bOffLane = (u32)(ln8 * BROW + (grp & 1) * 16 + (grp >> 1) * 32);

    // ---- act roles: lane = lay*16 + up*4 + ws; cells = (elems 2ws, 2ws+1) of unit 4wrp+up ----
    const int ws  = lane & 3;
    const int up  = (lane >> 2) & 3;
    const int lay = lane >> 4;             // 0 or 1
    const int au  = 4 * wrp + up;          // unit (valid if < 50)
    u32* gw32 = (u32*)(sm + SM_G) + wrp * 160;   // [2 lay][16 rows][5 half2-words]
    const int gwo = lay * 80 + (4 * up) * 5 + ws;      // t=0 word; +5 per gate
    const u32 wOff0 = (u32)((2 * ws) * BROW + (lay ? (59 + au) : (8 + au)) * 2);

    // ---- x staging roles: tid<64 -> (xe, xd); active only for xe<cnt ----
    const int xd = tid & 7, xe = tid >> 3;
    const bool doX = (tid < 64) && (xe < cnt);
    const float* xgp = doX ? (x + ((size_t)(start + xe) * TN) * 8 + xd) : x;

    __syncthreads();   // zeroing done

    // bias col 58 = 1.0 in both tiles; x(0) into buf0; prefetch x(1)
    if (tid < 16)
        *(__half*)(sm + SM_B + (tid >> 3) * BT + (tid & 7) * BROW + 58 * 2) = __float2half_rn(1.f);
    float xv = 0.f;
    if (doX){
        *(__half*)(sm + SM_B + xe * BROW + xd * 2) = __float2half_rn(xgp[0]);
        xv = xgp[8];
    }

    float cc0 = 0.f, cc1 = 0.f;    // c-state for this lane's two cells

    // ================= phase loop (one barrier per phase) =================
    for (int p = 0; p <= TN; ++p){
        const int b = p & 1, nb = b ^ 1;

        __syncthreads();   // B[b] ready; B[nb] free

        // ---------------- MMA: single pass fp16, N=8 ----------------
        float acc0[4] = {0,0,0,0};
        float acc1[4] = {0,0,0,0};
        {
            const u32 bhA = smb + SM_B + (u32)(b * BT) + bOffLane;
#pragma unroll
            for (int i = 0; i < 3; ++i){   // kt pairs {0,1},{2,3},{4,5}
                u32 bh[4];
                ldsm4(bh, bhA + i * 64);
                const int k0 = 2 * i, k1 = 2 * i + 1;
                mma_f16(acc1, A1[k0], bh[0], bh[1]);
                mma_f16(acc1, A1[k1], bh[2], bh[3]);
                if (k0 < 4) mma_f16(acc0, A0[k0], bh[0], bh[1]);
                if (k1 < 4) mma_f16(acc0, A0[k1], bh[2], bh[3]);
            }
            {   // kt 6 only (kt 7 is padding): x2 load
                u32 bh[2];
                ldsm2(bh, bhA + 192);
                mma_f16(acc1, A1[6], bh[0], bh[1]);
            }
        }

        // ---------------- gates -> warp-private scratch (half2) ----------------
        {
            const int j4 = lane & 3;
            const __half2 h00 = __floats2half2_rn(acc0[0], acc0[1]);
            const __half2 h01 = __floats2half2_rn(acc0[2], acc0[3]);
            const __half2 h10 = __floats2half2_rn(acc1[0], acc1[1]);
            const __half2 h11 = __floats2half2_rn(acc1[2], acc1[3]);
            gw32[gid * 5 + j4]            = *(const u32*)&h00;
            gw32[(gid + 8) * 5 + j4]      = *(const u32*)&h01;
            gw32[80 + gid * 5 + j4]       = *(const u32*)&h10;
            gw32[80 + (gid + 8) * 5 + j4] = *(const u32*)&h11;
        }
        __syncwarp(0xffffffffu);

        // ---------------- activations (warp-local; lane owns 2 cells, 1 layer) ----------------
        char* bwh = sm + SM_B + nb * BT;
        if (au < HN && (lay ? (p >= 1) : (p < TN))){
            const u32 wi = gw32[gwo];
            const u32 wf = gw32[gwo + 5];
            const u32 wg = gw32[gwo + 10];
            const u32 wo = gw32[gwo + 15];
            const float2 fi = __half22float2(*(const __half2*)&wi);
            const float2 ff = __half22float2(*(const __half2*)&wf);
            const float2 fg = __half22float2(*(const __half2*)&wg);
            const float2 fo = __half22float2(*(const __half2*)&wo);
            // cell 0 (elem 2ws)
            const float i0 = fmaf(0.5f, tanha(fi.x), 0.5f);
            const float f0 = fmaf(0.5f, tanha(ff.x), 0.5f);
            const float q0 = tanha(fg.x);
            const float o0 = fmaf(0.5f, tanha(fo.x), 0.5f);
            cc0 = fmaf(f0, cc0, i0 * q0);
            const float v0 = o0 * tanha(cc0);
            // cell 1 (elem 2ws+1)
            const float i1 = fmaf(0.5f, tanha(fi.y), 0.5f);
            const float f1 = fmaf(0.5f, tanha(ff.y), 0.5f);
            const float q1 = tanha(fg.y);
            const float o1 = fmaf(0.5f, tanha(fo.y), 0.5f);
            cc1 = fmaf(f1, cc1, i1 * q1);
            const float v1 = o1 * tanha(cc1);
            if (lay == 1 && p == TN){
                float* hd = (float*)(sm + SM_HEAD);
                hd[au * 8 + 2 * ws]     = v0;   // final h1 stash
                hd[au * 8 + 2 * ws + 1] = v1;
            } else {
                *(__half*)(bwh + wOff0)        = __float2half_rn(v0);
                *(__half*)(bwh + wOff0 + BROW) = __float2half_rn(v1);
            }
        }

        // ---------------- x staging: x(p+1) -> buf nb ----------------
        if (doX && (p + 1) < TN){
            *(__half*)(bwh + xe * BROW + xd * 2) = __float2half_rn(xv);
            int tn = p + 2; if (tn > TN - 1) tn = TN - 1;
            xv = xgp[(size_t)tn * 8];
        }
    }

    __syncthreads();

    // ---- linear head on stashed final h1 ----
    if (tid < cnt){
        const float* hd = (const float*)(sm + SM_HEAD);
        float acc = wl[HN];
#pragma unroll 10
        for (int j = 0; j < HN; ++j)
            acc = fmaf(hd[j * 8 + tid], wl[j], acc);
        out[start + tid] = acc;
    }
}

extern "C" void kernel_launch(void* const* d_in, const int* in_sizes, int n_in,
                              void* d_out, int out_size)
{
    const float* x    = (const float*)d_in[0];
    const float* Wih0 = (const float*)d_in[1];
    const float* Whh0 = (const float*)d_in[2];
    const float* bih0 = (const float*)d_in[3];
    const float* bhh0 = (const float*)d_in[4];
    const float* Wih1 = (const float*)d_in[5];
    const float* Whh1 = (const float*)d_in[6];
    const float* bih1 = (const float*)d_in[7];
    const float* bhh1 = (const float*)d_in[8];
    const float* Wlin = (const float*)d_in[9];
    const float* blin = (const float*)d_in[10];
    float* out = (float*)d_out;

    cudaFuncSetAttribute(lstm_mma10_kernel,
                         cudaFuncAttributeMaxDynamicSharedMemorySize, SMEM_BYTES);
    lstm_mma10_kernel<<<NCTA, NTHR, SMEM_BYTES>>>(
        x, Wih0, Whh0, bih0, bhh0, Wih1, Whh1, bih1, bhh1, Wlin, blin, out);
}